// round 3
// baseline (speedup 1.0000x reference)
#include <cuda_runtime.h>
#include <cstdint>

// PyramidROIAlign:
//   boxes: (2, 1000, 4) f32  [y1, x1, y2, x2] normalized
//   p2..p5: (2, S, S, 256) f32, S = 256/128/64/32, NHWC
//   out:  (2, 1000, 7, 7, 256) f32
//
// Block = one ROI (2000 blocks x 256 threads).
// Per-point scalar math hoisted into smem once (49 entries).
// Hot loop: each warp owns one pool point per iteration; each lane handles
// channels (lane, lane+32) -> 8 batched LDG.128 per thread per iteration
// (high MLP), 16 FFMA pairs, 2 streaming STG.128 (__stcs: keep L2 for reads).

#define BATCH   2
#define NROI    1000
#define POOLH   7
#define POOLW   7
#define NCH     256
#define NCH4    (NCH / 4)          // 64
#define POINTS  (POOLH * POOLW)    // 49
#define ELEMS   (POINTS * NCH4)    // 3136

struct PtParams {
    const float4* p00;
    const float4* p01;
    const float4* p10;
    const float4* p11;
    float wx, wy;
};

__device__ __forceinline__ float4 lerp2(const float4 v00, const float4 v01,
                                        const float4 v10, const float4 v11,
                                        const float wx, const float wy)
{
    float4 r;
    float t, bo;
    t  = v00.x + wx * (v01.x - v00.x);
    bo = v10.x + wx * (v11.x - v10.x);
    r.x = t + wy * (bo - t);
    t  = v00.y + wx * (v01.y - v00.y);
    bo = v10.y + wx * (v11.y - v10.y);
    r.y = t + wy * (bo - t);
    t  = v00.z + wx * (v01.z - v00.z);
    bo = v10.z + wx * (v11.z - v10.z);
    r.z = t + wy * (bo - t);
    t  = v00.w + wx * (v01.w - v00.w);
    bo = v10.w + wx * (v11.w - v10.w);
    r.w = t + wy * (bo - t);
    return r;
}

__global__ __launch_bounds__(256) void pyramid_roi_align_kernel(
    const float* __restrict__ boxes,
    const float* __restrict__ p2,
    const float* __restrict__ p3,
    const float* __restrict__ p4,
    const float* __restrict__ p5,
    float4* __restrict__ out)
{
    __shared__ PtParams pts[POINTS];

    const int roi = blockIdx.x;          // 0..1999
    const int tid = threadIdx.x;
    const int b = roi >= NROI ? 1 : 0;

    if (tid < POINTS) {
        const int py = tid / POOLW;
        const int px = tid - py * POOLW;

        const float4 bx = __ldg((const float4*)(boxes) + roi);
        const float y1 = bx.x, x1 = bx.y, y2 = bx.z, x2 = bx.w;
        const float h = y2 - y1;
        const float w = x2 - x1;

        // roi_level = clip(round(log2(sqrt(max(h*w,1e-12)) / (224/1024))), 2, 5)
        // rintf = round-half-to-even, matches jnp.round.
        const float lvlf = log2f(sqrtf(fmaxf(h * w, 1e-12f)) / 0.21875f);
        int level = (int)rintf(lvlf);
        level = min(max(level, 2), 5);

        const float* feat;
        int H;
        if (level == 2)      { feat = p2; H = 256; }
        else if (level == 3) { feat = p3; H = 128; }
        else if (level == 4) { feat = p4; H = 64;  }
        else                 { feat = p5; H = 32;  }

        const float Hm1 = (float)(H - 1);
        const float ty = (float)py * (1.0f / 6.0f);
        const float tx = (float)px * (1.0f / 6.0f);
        const float ysf = (y1 + h * ty) * Hm1;
        const float xsf = (x1 + w * tx) * Hm1;

        const float y0f = floorf(ysf);
        const float x0f = floorf(xsf);
        const float wy = ysf - y0f;   // weights from UNCLAMPED floor (matches ref)
        const float wx = xsf - x0f;

        const int y0  = min(max((int)y0f, 0), H - 1);
        const int y1i = min(max((int)y0f + 1, 0), H - 1);
        const int x0  = min(max((int)x0f, 0), H - 1);
        const int x1i = min(max((int)x0f + 1, 0), H - 1);

        // NHWC float4 view: feat4[((b*H + y)*H + x)*64 + c]
        const float4* f4 = (const float4*)feat;
        const int rowb0 = (b * H + y0)  * H;
        const int rowb1 = (b * H + y1i) * H;
        PtParams P;
        P.p00 = f4 + (rowb0 + x0 ) * NCH4;
        P.p01 = f4 + (rowb0 + x1i) * NCH4;
        P.p10 = f4 + (rowb1 + x0 ) * NCH4;
        P.p11 = f4 + (rowb1 + x1i) * NCH4;
        P.wx = wx;
        P.wy = wy;
        pts[tid] = P;
    }
    __syncthreads();

    float4* __restrict__ outb = out + (long long)roi * ELEMS;

    const int wrp  = tid >> 5;   // 0..7
    const int lane = tid & 31;

    // 6 iterations x 8 warps = points 0..47; each lane does channels lane, lane+32.
    #pragma unroll
    for (int i = 0; i < 6; i++) {
        const int p = i * 8 + wrp;
        const PtParams P = pts[p];

        // Batch all 8 loads before any compute -> 8 outstanding LDG.128/thread.
        const float4 a00 = __ldg(P.p00 + lane);
        const float4 a01 = __ldg(P.p01 + lane);
        const float4 a10 = __ldg(P.p10 + lane);
        const float4 a11 = __ldg(P.p11 + lane);
        const float4 b00 = __ldg(P.p00 + lane + 32);
        const float4 b01 = __ldg(P.p01 + lane + 32);
        const float4 b10 = __ldg(P.p10 + lane + 32);
        const float4 b11 = __ldg(P.p11 + lane + 32);

        const float4 ra = lerp2(a00, a01, a10, a11, P.wx, P.wy);
        const float4 rb = lerp2(b00, b01, b10, b11, P.wx, P.wy);

        __stcs(outb + p * NCH4 + lane,      ra);
        __stcs(outb + p * NCH4 + lane + 32, rb);
    }

    // Tail: point 48 (64 float4), warps 0-1.
    if (tid < NCH4) {
        const PtParams P = pts[POINTS - 1];
        const float4 v00 = __ldg(P.p00 + tid);
        const float4 v01 = __ldg(P.p01 + tid);
        const float4 v10 = __ldg(P.p10 + tid);
        const float4 v11 = __ldg(P.p11 + tid);
        const float4 r = lerp2(v00, v01, v10, v11, P.wx, P.wy);
        __stcs(outb + (POINTS - 1) * NCH4 + tid, r);
    }
}

extern "C" void kernel_launch(void* const* d_in, const int* in_sizes, int n_in,
                              void* d_out, int out_size)
{
    const float* boxes = (const float*)d_in[0];
    const float* p2    = (const float*)d_in[1];
    const float* p3    = (const float*)d_in[2];
    const float* p4    = (const float*)d_in[3];
    const float* p5    = (const float*)d_in[4];
    float4* out = (float4*)d_out;

    pyramid_roi_align_kernel<<<BATCH * NROI, 256>>>(boxes, p2, p3, p4, p5, out);
}